// round 17
// baseline (speedup 1.0000x reference)
#include <cuda_runtime.h>
#include <cuda_fp16.h>
#include <cstdint>

// Problem constants: B=64, T=12, P=128, F=128, H=12, MAXC=48
#define Bdim   64
#define Tdim   12
#define Pdim   128
#define Fdim   128
#define Hdim   12
#define MAXC   48
#define Ddim   (Tdim * Fdim)        // 1536 (K)
#define NCdim  (MAXC * Hdim)        // 576  (GEMM N)
#define NNODES 4356

#define TN 96                       // c-tile (576 = 6*96)
#define NTILES (6 * Pdim)           // 768 work units
#define TK 32                       // K chunk (2 k16 steps)
#define NKC (Ddim / TK)             // 48
#define NTHREADS 256                // 8 warps: 2(M) x 4(N), each 32m x 24n
#define ASTR 40                     // fp16 row stride As[m][k]
#define BSTR 104                    // fp16 row stride Bs[k][c]
#define GRID_PERSIST 444            // 148 SMs x 3 resident CTAs

__device__ int g_tile_counter;

__global__ void reset_counter_kernel() { g_tile_counter = 0; }

__device__ __forceinline__ unsigned smem_u32(const void* p) {
    return (unsigned)__cvta_generic_to_shared(p);
}
__device__ __forceinline__ unsigned pack2h(float x, float y) {
    __half2 h = __floats2half2_rn(x, y);
    return *reinterpret_cast<unsigned*>(&h);
}
__device__ __forceinline__ void ldmx4(unsigned* r, unsigned addr) {
    asm volatile("ldmatrix.sync.aligned.m8n8.x4.shared.b16 {%0,%1,%2,%3}, [%4];"
                 : "=r"(r[0]), "=r"(r[1]), "=r"(r[2]), "=r"(r[3]) : "r"(addr));
}
__device__ __forceinline__ void ldmx4t(unsigned* r, unsigned addr) {
    asm volatile("ldmatrix.sync.aligned.m8n8.x4.trans.shared.b16 {%0,%1,%2,%3}, [%4];"
                 : "=r"(r[0]), "=r"(r[1]), "=r"(r[2]), "=r"(r[3]) : "r"(addr));
}
__device__ __forceinline__ void ldmx2t(unsigned* r, unsigned addr) {
    asm volatile("ldmatrix.sync.aligned.m8n8.x2.trans.shared.b16 {%0,%1}, [%2];"
                 : "=r"(r[0]), "=r"(r[1]) : "r"(addr));
}
__device__ __forceinline__ void mma_f16(float* c, const unsigned* a, unsigned b0, unsigned b1) {
    asm volatile(
        "mma.sync.aligned.m16n8k16.row.col.f32.f16.f16.f32 "
        "{%0,%1,%2,%3}, {%4,%5,%6,%7}, {%8,%9}, {%0,%1,%2,%3};"
        : "+f"(c[0]), "+f"(c[1]), "+f"(c[2]), "+f"(c[3])
        : "r"(a[0]), "r"(a[1]), "r"(a[2]), "r"(a[3]), "r"(b0), "r"(b1));
}

// min 3 CTAs/SM -> 85-reg cap -> 24 warps/SM
__global__ __launch_bounds__(NTHREADS, 3)
void patch_readout_f16_persist_kernel(
    const float* __restrict__ x,        // [B, T, P, F]
    const float* __restrict__ W,        // [P, D, 576]
    const float* __restrict__ bias,     // [P, 576]
    const int*   __restrict__ node_map, // [P, MAXC]
    float*       __restrict__ out)      // [NNODES * B, H]
{
    const int tid  = threadIdx.x;
    const int lane = tid & 31;
    const int warp = tid >> 5;
    const int g    = lane >> 2;
    const int t    = lane & 3;
    const int m_base = (warp >> 2) * 32;   // 2 M-groups of 32 rows
    const int n_base = (warp & 3) * 24;    // 4 N-groups of 24 cols

    __shared__ __align__(16) __half AsH[2][64][ASTR];   // x fp16
    __shared__ __align__(16) __half BsH[2][TK][BSTR];   // W fp16
    __shared__ int s_tile;

    const unsigned aHB = smem_u32(AsH);
    const unsigned bHB = smem_u32(BsH);
    const unsigned ABUF = 64 * ASTR * 2;
    const unsigned BBUF = TK * BSTR * 2;

    // ---- fill roles ----
    const int a_m  = tid >> 2;          // 0..63 batch row
    const int a_kq = (tid & 3) * 8;     // k octet
    const int b_d  = tid >> 3;          // 0..31 W row within chunk
    const int b_c  = (tid & 7) * 4;     // c quad base; +32*i (i=0..2)
    const long long a_row_off = (long long)a_m * (Tdim * Pdim * Fdim);

    // ---- ldmatrix per-lane address terms ----
    const int q  = lane >> 3;
    const int j7 = lane & 7;
    int rowTermA[2];
    {
        const int rq = (q & 1) * 8 + j7;
        const int cq = (q >> 1) * 8;
        rowTermA[0] = (m_base +  0 + rq) * ASTR + cq;
        rowTermA[1] = (m_base + 16 + rq) * ASTR + cq;
    }
    const int rowTermB4 = ((q & 1) * 8 + j7) * BSTR + n_base + (q >> 1) * 8;
    const int rowTermB2 = (((lane >> 3) & 1) * 8 + j7) * BSTR + n_base + 16;

    for (;;) {
        // ---- grab next tile ----
        if (tid == 0) s_tile = atomicAdd(&g_tile_counter, 1);
        __syncthreads();                 // broadcast tile id; also guards smem reuse
        const int tile = s_tile;
        if (tile >= NTILES) break;
        const int p  = tile >> 3;        // 768 = 128p * 6c ; encode: tile = p*6 + c? use div
        // NOTE: 6 tiles per p -> decode properly:
        const int pp = tile / 6;
        const int C0 = (tile - pp * 6) * TN;

        const float* xp = x + pp * Fdim;
        const float* Wp = W + (long long)pp * Ddim * NCdim;

        float acc[2][3][4];
        #pragma unroll
        for (int i = 0; i < 2; i++)
            #pragma unroll
            for (int jj = 0; jj < 3; jj++)
                #pragma unroll
                for (int r = 0; r < 4; r++) acc[i][jj][r] = 0.0f;

        float4 av0, av1, bq0, bq1, bq2;

        auto load_chunk = [&](int kc) {
            const int K0 = kc * TK;
            const int tt = K0 >> 7;
            const int f0 = K0 & 127;
            const float* ap = xp + a_row_off + tt * (Pdim * Fdim) + f0 + a_kq;
            av0 = *reinterpret_cast<const float4*>(ap);
            av1 = *reinterpret_cast<const float4*>(ap + 4);
            const float* bp = Wp + (long long)(K0 + b_d) * NCdim + C0 + b_c;
            bq0 = *reinterpret_cast<const float4*>(bp);
            bq1 = *reinterpret_cast<const float4*>(bp + 32);
            bq2 = *reinterpret_cast<const float4*>(bp + 64);
        };
        auto store_chunk = [&](int buf) {
            *reinterpret_cast<uint4*>(&AsH[buf][a_m][a_kq]) =
                make_uint4(pack2h(av0.x, av0.y), pack2h(av0.z, av0.w),
                           pack2h(av1.x, av1.y), pack2h(av1.z, av1.w));
            *reinterpret_cast<uint2*>(&BsH[buf][b_d][b_c]) =
                make_uint2(pack2h(bq0.x, bq0.y), pack2h(bq0.z, bq0.w));
            *reinterpret_cast<uint2*>(&BsH[buf][b_d][b_c + 32]) =
                make_uint2(pack2h(bq1.x, bq1.y), pack2h(bq1.z, bq1.w));
            *reinterpret_cast<uint2*>(&BsH[buf][b_d][b_c + 64]) =
                make_uint2(pack2h(bq2.x, bq2.y), pack2h(bq2.z, bq2.w));
        };

        load_chunk(0);
        store_chunk(0);
        __syncthreads();

        for (int kc = 0; kc < NKC; kc++) {
            const int buf = kc & 1;
            const bool more = (kc + 1 < NKC);
            if (more) load_chunk(kc + 1);

            #pragma unroll
            for (int s = 0; s < 2; s++) {
                const int k0 = s * 16;
                unsigned aH[2][4], bH4[4], bH2[2];
                #pragma unroll
                for (int i = 0; i < 2; i++) {
                    const unsigned ao = buf * ABUF + (unsigned)(rowTermA[i] + k0) * 2u;
                    ldmx4(aH[i], aHB + ao);
                }
                {
                    const unsigned bo4 = buf * BBUF + (unsigned)(rowTermB4 + k0 * BSTR) * 2u;
                    ldmx4t(bH4, bHB + bo4);
                    const unsigned bo2 = buf * BBUF + (unsigned)(rowTermB2 + k0 * BSTR) * 2u;
                    ldmx2t(bH2, bHB + bo2);
                }
                #pragma unroll
                for (int i = 0; i < 2; i++) {
                    mma_f16(acc[i][0], aH[i], bH4[0], bH4[1]);
                    mma_f16(acc[i][1], aH[i], bH4[2], bH4[3]);
                    mma_f16(acc[i][2], aH[i], bH2[0], bH2[1]);
                }
            }

            if (more) {
                store_chunk(buf ^ 1);
                __syncthreads();
            }
        }

        // ---- epilogue: bias + permutation scatter ----
        const int*   nm = node_map + pp * MAXC;
        const float* bp = bias + pp * NCdim;

        #pragma unroll
        for (int jj = 0; jj < 3; jj++) {
            const int cbase = C0 + n_base + jj * 8 + 2 * t;
            #pragma unroll
            for (int e = 0; e < 2; e++) {
                const int c = cbase + e;
                const int n = c / Hdim;
                const int h = c - n * Hdim;
                const int node = nm[n];
                if (node < NNODES) {
                    const float bb = bp[c];
                    float* op = out + (long long)node * (Bdim * Hdim) + h;
                    #pragma unroll
                    for (int i = 0; i < 2; i++) {
                        const int r0 = m_base + i * 16 + g;
                        op[(r0    ) * Hdim] = acc[i][jj][e]     + bb;
                        op[(r0 + 8) * Hdim] = acc[i][jj][2 + e] + bb;
                    }
                }
            }
        }
        // loop back: sync at top guards smem buffer reuse across tiles
    }
}

extern "C" void kernel_launch(void* const* d_in, const int* in_sizes, int n_in,
                              void* d_out, int out_size)
{
    const float* x        = (const float*)d_in[0];
    const float* W        = (const float*)d_in[1];
    const float* bias     = (const float*)d_in[2];
    const int*   node_map = (const int*)d_in[3];
    float*       out      = (float*)d_out;

    reset_counter_kernel<<<1, 1>>>();
    patch_readout_f16_persist_kernel<<<GRID_PERSIST, NTHREADS>>>(x, W, bias, node_map, out);
}